// round 13
// baseline (speedup 1.0000x reference)
#include <cuda_runtime.h>
#include <cstdint>
#include <cmath>

// Problem constants (fixed by the dataset)
#define T_TOK 1024
#define H_DIM 2048
#define I_DIM 768
#define E_NUM 8
#define K_TOP 2
#define NROWS (T_TOK * K_TOP)      // 2048 permuted rows

#define BM 128
#define MAX_TILES 24               // sum_e ceil(cnt_e/128) <= 23

// ---------------- scratch (no allocations allowed) ----------------
__device__ int   g_row_src[NROWS];
__device__ int   g_pos[NROWS];
__device__ int   g_tile_expert[MAX_TILES];
__device__ int   g_tile_row[MAX_TILES];
__device__ int   g_tile_end[MAX_TILES];
__device__ int   g_num_tiles;
__device__ float g_xc[T_TOK * H_DIM];     // tf32-rounded hidden_states
__device__ float g_act[NROWS * I_DIM];    // tf32-rounded swiglu output
__device__ float g_fc2h0[NROWS * H_DIM];  // fc2 K-half 0
__device__ float g_fc2h1[NROWS * H_DIM];  // fc2 K-half 1

// ---------------- PTX helpers (all sm_80-level, no 'a' features) ----------------
__device__ __forceinline__ uint32_t s2u(const void* p) {
    uint32_t a;
    asm("{ .reg .u64 t; cvta.to.shared.u64 t, %1; cvt.u32.u64 %0, t; }" : "=r"(a) : "l"(p));
    return a;
}
__device__ __forceinline__ void cp16(uint32_t dst, const void* src, uint32_t sz) {
    asm volatile("cp.async.cg.shared.global [%0], [%1], 16, %2;" :: "r"(dst), "l"(src), "r"(sz));
}
__device__ __forceinline__ void cp_commit() { asm volatile("cp.async.commit_group;" ::: "memory"); }
template<int N> __device__ __forceinline__ void cp_wait() {
    asm volatile("cp.async.wait_group %0;" :: "n"(N) : "memory");
}
__device__ __forceinline__ void ldsm4(uint32_t r[4], uint32_t addr) {
    asm volatile("ldmatrix.sync.aligned.m8n8.x4.shared.b16 {%0,%1,%2,%3}, [%4];"
        : "=r"(r[0]), "=r"(r[1]), "=r"(r[2]), "=r"(r[3]) : "r"(addr));
}
__device__ __forceinline__ uint32_t f2tf_f(float x) {
    uint32_t r;
    asm("cvt.rna.tf32.f32 %0, %1;" : "=r"(r) : "f"(x));
    return r;
}
__device__ __forceinline__ float tfr(float x) {
    return __uint_as_float(f2tf_f(x));
}
__device__ __forceinline__ void mma8(float* c, const uint32_t* a, uint32_t b0, uint32_t b1) {
    asm volatile(
        "mma.sync.aligned.m16n8k8.row.col.f32.tf32.tf32.f32 "
        "{%0,%1,%2,%3}, {%4,%5,%6,%7}, {%8,%9}, {%0,%1,%2,%3};"
        : "+f"(c[0]), "+f"(c[1]), "+f"(c[2]), "+f"(c[3])
        : "r"(a[0]), "r"(a[1]), "r"(a[2]), "r"(a[3]), "r"(b0), "r"(b1));
}

// SMEM: 3 stages of {A 16KB (128x32f swizzled), B 17408B (32 x 136 f)}
#define BPAD 136
#define STG 33792
#define SMEM_TOTAL 101376
#define OFF_A(b) ((b) * STG)
#define OFF_B(b) (OFF_A(b) + 16384)

// ---------------- setup: counting sort + BM=128 tiling ----------------
__global__ void setup_kernel(const int* __restrict__ sel) {
    __shared__ int cnt[E_NUM];
    __shared__ int run[E_NUM];
    int tid = threadIdx.x;
    if (tid < E_NUM) cnt[tid] = 0;
    __syncthreads();
    for (int i = tid; i < NROWS; i += blockDim.x)
        atomicAdd(&cnt[sel[i]], 1);
    __syncthreads();
    if (tid == 0) {
        int s = 0, nt = 0;
        for (int e = 0; e < E_NUM; e++) {
            run[e] = s;
            int c = cnt[e];
            for (int r = 0; r < c; r += BM) {
                g_tile_expert[nt] = e;
                g_tile_row[nt]    = s + r;
                g_tile_end[nt]    = s + c;
                nt++;
            }
            s += c;
        }
        g_num_tiles = nt;
    }
    __syncthreads();
    for (int i = tid; i < NROWS; i += blockDim.x) {
        int e = sel[i];
        int p = atomicAdd(&run[e], 1);
        g_row_src[p] = i;
        g_pos[i] = p;
    }
}

// ---------------- cvtx: g_xc = tf32(x) ----------------
__global__ void __launch_bounds__(256)
cvtx_kernel(const float* __restrict__ x) {
    int i = blockIdx.x * blockDim.x + threadIdx.x;
    if (i >= T_TOK * (H_DIM / 4)) return;
    float4 v = reinterpret_cast<const float4*>(x)[i];
    v.x = tfr(v.x); v.y = tfr(v.y); v.z = tfr(v.z); v.w = tfr(v.w);
    reinterpret_cast<float4*>(g_xc)[i] = v;
}

// ---------------- GEMM1: act = swiglu( Xc_gather @ W1[e] ) ----------------
// 128 threads, tile 128 x (gate64 + up64). 4 warps 2x2, warp tile 64x64.
__global__ void __launch_bounds__(128, 2)
gemm1_kernel(const float* __restrict__ w1) {
    extern __shared__ char smem[];
    uint32_t sb = s2u(smem);
    int mt = blockIdx.x;
    if (mt >= g_num_tiles) return;
    int e = g_tile_expert[mt], row0 = g_tile_row[mt], rend = g_tile_end[mt];
    int col0g = blockIdx.y * 64;

    int tid = threadIdx.x, lane = tid & 31, wid = tid >> 5;
    int warpM = wid >> 1, warpN = wid & 1;
    int gid = lane >> 2, tig = lane & 3;
    int mlane = lane & 15, extra = lane >> 4, key = lane & 7;

    const float* W = w1 + (size_t)e * H_DIM * (2 * I_DIM);

    // A loader: each thread owns row `tid` of the 128-row tile
    int arow = row0 + tid;
    int tokm = (arow < rend) ? (g_row_src[arow] / K_TOP) : -1;
    const float* asrc = g_xc + (size_t)(tokm < 0 ? 0 : tokm) * H_DIM;
    uint32_t asz = (tokm < 0) ? 0u : 16u;
    int akey = tid & 7;

    auto load_chunk = [&](int ci, int buf) {
        int k0 = ci * 32;
        uint32_t Ab = sb + OFF_A(buf);
        #pragma unroll
        for (int c = 0; c < 8; c++)
            cp16(Ab + tid * 128 + ((c ^ akey) << 4), asrc + k0 + c * 4, asz);
        uint32_t Bb = sb + OFF_B(buf);
        #pragma unroll
        for (int q = 0; q < 8; q++) {
            int idx = tid + 128 * q;
            int k = idx >> 5, n = (idx & 31) * 4;
            const float* src = (n < 64)
                ? W + (size_t)(k0 + k) * (2 * I_DIM) + col0g + n
                : W + (size_t)(k0 + k) * (2 * I_DIM) + I_DIM + col0g + (n - 64);
            cp16(Bb + k * (BPAD * 4) + n * 4, src, 16);
        }
        cp_commit();
    };

    int boff = tig * BPAD + warpN * 64 + gid;

    float acc[4][8][4] = {};
    const int NC = H_DIM / 32;   // 64
    load_chunk(0, 0);
    load_chunk(1, 1);
    int bc = 0;
    for (int i = 0; i < NC; i++) {
        cp_wait<1>();
        __syncthreads();
        int bn = bc + 2; if (bn >= 3) bn -= 3;
        if (i + 2 < NC) load_chunk(i + 2, bn);
        else            cp_commit();

        uint32_t Ab = sb + OFF_A(bc);
        const float* Bsp = (const float*)(smem + OFF_B(bc));
        #pragma unroll
        for (int ks = 0; ks < 4; ks++) {
            uint32_t a[4][4];
            #pragma unroll
            for (int mi = 0; mi < 4; mi++) {
                uint32_t addr = Ab + (uint32_t)((warpM * 64 + mi * 16 + mlane) * 128
                              + ((((ks << 1) | extra) ^ key) << 4));
                ldsm4(a[mi], addr);
            }
            #pragma unroll
            for (int j = 0; j < 8; j++) {
                uint32_t b0 = f2tf_f(Bsp[boff + ks * (8 * BPAD) + j * 8]);
                uint32_t b1 = f2tf_f(Bsp[boff + ks * (8 * BPAD) + j * 8 + 4 * BPAD]);
                #pragma unroll
                for (int mi = 0; mi < 4; mi++)
                    mma8(acc[mi][j], a[mi], b0, b1);
            }
        }
        bc = (bc + 1 == 3) ? 0 : bc + 1;
    }

    // epilogue: frags -> smem roundtrip, swiglu (tf32-rounded) -> g_act
    __syncthreads();
    float* Es = (float*)smem;          // 128 x 132
    #pragma unroll
    for (int mi = 0; mi < 4; mi++)
        #pragma unroll
        for (int j = 0; j < 8; j++) {
            int row = warpM * 64 + mi * 16 + gid;
            int col = warpN * 64 + j * 8 + 2 * tig;
            *(float2*)&Es[row * 132 + col]       = make_float2(acc[mi][j][0], acc[mi][j][1]);
            *(float2*)&Es[(row + 8) * 132 + col] = make_float2(acc[mi][j][2], acc[mi][j][3]);
        }
    __syncthreads();

    int r = row0 + tid;
    if (r < rend) {
        float* dst = g_act + (size_t)r * I_DIM + col0g;
        #pragma unroll
        for (int jj = 0; jj < 64; jj += 4) {
            float4 gv = *(float4*)&Es[tid * 132 + jj];
            float4 uv = *(float4*)&Es[tid * 132 + 64 + jj];
            float4 o;
            o.x = tfr(gv.x * (1.0f / (1.0f + __expf(-gv.x))) * uv.x);
            o.y = tfr(gv.y * (1.0f / (1.0f + __expf(-gv.y))) * uv.y);
            o.z = tfr(gv.z * (1.0f / (1.0f + __expf(-gv.z))) * uv.z);
            o.w = tfr(gv.w * (1.0f / (1.0f + __expf(-gv.w))) * uv.w);
            *(float4*)(dst + jj) = o;
        }
    }
}

// ---------------- GEMM2: fc2_half[z] = act @ W2[e][z-half] ----------------
// 128 threads, tile 128x128, 4 warps 2x2, warp tile 64x64, split-K2.
__global__ void __launch_bounds__(128, 2)
gemm2_kernel(const float* __restrict__ w2) {
    extern __shared__ char smem[];
    uint32_t sb = s2u(smem);
    int mt = blockIdx.x;
    if (mt >= g_num_tiles) return;
    int e = g_tile_expert[mt], row0 = g_tile_row[mt], rend = g_tile_end[mt];
    int col0 = blockIdx.y * 128;
    int kz = blockIdx.z;
    const int KH = I_DIM / 2;          // 384

    int tid = threadIdx.x, lane = tid & 31, wid = tid >> 5;
    int warpM = wid >> 1, warpN = wid & 1;
    int gid = lane >> 2, tig = lane & 3;
    int mlane = lane & 15, extra = lane >> 4, key = lane & 7;

    const float* W = w2 + (size_t)e * I_DIM * H_DIM + (size_t)(kz * KH) * H_DIM + col0;

    int rr = row0 + tid; if (rr >= NROWS) rr = NROWS - 1;   // clamp; masked later
    const float* asrc = g_act + (size_t)rr * I_DIM + kz * KH;
    int akey = tid & 7;

    auto load_chunk = [&](int ci, int buf) {
        int k0 = ci * 32;
        uint32_t Ab = sb + OFF_A(buf);
        #pragma unroll
        for (int c = 0; c < 8; c++)
            cp16(Ab + tid * 128 + ((c ^ akey) << 4), asrc + k0 + c * 4, 16);
        uint32_t Bb = sb + OFF_B(buf);
        #pragma unroll
        for (int q = 0; q < 8; q++) {
            int idx = tid + 128 * q;
            int k = idx >> 5, n = (idx & 31) * 4;
            cp16(Bb + k * (BPAD * 4) + n * 4, W + (size_t)(k0 + k) * H_DIM + n, 16);
        }
        cp_commit();
    };

    int boff = tig * BPAD + warpN * 64 + gid;

    float acc[4][8][4] = {};
    const int NC = KH / 32;            // 12
    load_chunk(0, 0);
    load_chunk(1, 1);
    int bc = 0;
    for (int i = 0; i < NC; i++) {
        cp_wait<1>();
        __syncthreads();
        int bn = bc + 2; if (bn >= 3) bn -= 3;
        if (i + 2 < NC) load_chunk(i + 2, bn);
        else            cp_commit();

        uint32_t Ab = sb + OFF_A(bc);
        const float* Bsp = (const float*)(smem + OFF_B(bc));
        #pragma unroll
        for (int ks = 0; ks < 4; ks++) {
            uint32_t a[4][4];
            #pragma unroll
            for (int mi = 0; mi < 4; mi++) {
                uint32_t addr = Ab + (uint32_t)((warpM * 64 + mi * 16 + mlane) * 128
                              + ((((ks << 1) | extra) ^ key) << 4));
                ldsm4(a[mi], addr);
            }
            #pragma unroll
            for (int j = 0; j < 8; j++) {
                uint32_t b0 = f2tf_f(Bsp[boff + ks * (8 * BPAD) + j * 8]);
                uint32_t b1 = f2tf_f(Bsp[boff + ks * (8 * BPAD) + j * 8 + 4 * BPAD]);
                #pragma unroll
                for (int mi = 0; mi < 4; mi++)
                    mma8(acc[mi][j], a[mi], b0, b1);
            }
        }
        bc = (bc + 1 == 3) ? 0 : bc + 1;
    }

    // epilogue: direct stores into this K-half's buffer
    float* outb = kz ? g_fc2h1 : g_fc2h0;
    #pragma unroll
    for (int mi = 0; mi < 4; mi++) {
        int row = row0 + warpM * 64 + mi * 16 + gid;
        #pragma unroll
        for (int j = 0; j < 8; j++) {
            int col = col0 + warpN * 64 + j * 8 + 2 * tig;
            if (row < rend)
                *(float2*)&outb[(size_t)row * H_DIM + col] =
                    make_float2(acc[mi][j][0], acc[mi][j][1]);
            if (row + 8 < rend)
                *(float2*)&outb[(size_t)(row + 8) * H_DIM + col] =
                    make_float2(acc[mi][j][2], acc[mi][j][3]);
        }
    }
}

// ---------------- combine: out[t] = w0*(h0+h1)[p0] + w1*(h0+h1)[p1] ----------------
__global__ void __launch_bounds__(256)
combine_kernel(const float* __restrict__ rw, float* __restrict__ out) {
    int i = blockIdx.x * blockDim.x + threadIdx.x;
    if (i >= T_TOK * (H_DIM / 4)) return;
    int t  = i >> 9;
    int h4 = i & 511;
    int p0 = g_pos[2 * t];
    int p1 = g_pos[2 * t + 1];
    float w0 = rw[2 * t];
    float w1 = rw[2 * t + 1];
    size_t o0 = (size_t)p0 * H_DIM + h4 * 4;
    size_t o1 = (size_t)p1 * H_DIM + h4 * 4;
    float4 a0 = *(const float4*)&g_fc2h0[o0];
    float4 b0 = *(const float4*)&g_fc2h1[o0];
    float4 a1 = *(const float4*)&g_fc2h0[o1];
    float4 b1 = *(const float4*)&g_fc2h1[o1];
    float4 o;
    o.x = w0 * (a0.x + b0.x) + w1 * (a1.x + b1.x);
    o.y = w0 * (a0.y + b0.y) + w1 * (a1.y + b1.y);
    o.z = w0 * (a0.z + b0.z) + w1 * (a1.z + b1.z);
    o.w = w0 * (a0.w + b0.w) + w1 * (a1.w + b1.w);
    reinterpret_cast<float4*>(out)[i] = o;
}

// ---------------- launch ----------------
extern "C" void kernel_launch(void* const* d_in, const int* in_sizes, int n_in,
                              void* d_out, int out_size) {
    const float* x   = (const float*)d_in[0];   // hidden_states [T, H]
    const float* rw  = (const float*)d_in[1];   // routing_weights [T, K]
    const float* w1  = (const float*)d_in[2];   // gate_up_proj [E, H, 2I]
    const float* w2  = (const float*)d_in[3];   // down_proj   [E, I, H]
    const int*   sel = (const int*)d_in[4];     // selected_experts [T, K]
    float* out = (float*)d_out;                 // [T, H] fp32

    cudaFuncSetAttribute(gemm1_kernel, cudaFuncAttributeMaxDynamicSharedMemorySize, SMEM_TOTAL);
    cudaFuncSetAttribute(gemm2_kernel, cudaFuncAttributeMaxDynamicSharedMemorySize, SMEM_TOTAL);

    setup_kernel<<<1, 256>>>(sel);
    cvtx_kernel<<<(T_TOK * H_DIM / 4 + 255) / 256, 256>>>(x);
    gemm1_kernel<<<dim3(MAX_TILES, I_DIM / 64), 128, SMEM_TOTAL>>>(w1);
    gemm2_kernel<<<dim3(MAX_TILES, H_DIM / 128, 2), 128, SMEM_TOTAL>>>(w2);
    combine_kernel<<<(T_TOK * H_DIM / 4 + 255) / 256, 256>>>(rw, out);
}

// round 14
// speedup vs baseline: 1.4815x; 1.4815x over previous
#include <cuda_runtime.h>
#include <cstdint>
#include <cmath>

// Problem constants (fixed by the dataset)
#define T_TOK 1024
#define H_DIM 2048
#define I_DIM 768
#define E_NUM 8
#define K_TOP 2
#define NROWS (T_TOK * K_TOP)      // 2048 permuted rows

#define BM1 64
#define MAX_TILES 40               // BM=64: sum_e ceil(cnt_e/64) <= 39; BM=128 <= 24

// ---------------- scratch (no allocations allowed) ----------------
__device__ int   g_row_src[NROWS];
__device__ int   g_pos[NROWS];
__device__ int   g_tile_expert[MAX_TILES];   // BM=64 tiling (gemm1)
__device__ int   g_tile_row[MAX_TILES];
__device__ int   g_tile_end[MAX_TILES];
__device__ int   g_num_tiles;
__device__ int   g_tile2_expert[MAX_TILES];  // BM=128 tiling (gemm2)
__device__ int   g_tile2_row[MAX_TILES];
__device__ int   g_tile2_end[MAX_TILES];
__device__ int   g_num_tiles2;
__device__ float g_xc[T_TOK * H_DIM];     // tf32-rounded hidden_states
__device__ float g_act[NROWS * I_DIM];    // tf32-rounded swiglu output
__device__ float g_fc2h0[NROWS * H_DIM];  // fc2 K-half 0
__device__ float g_fc2h1[NROWS * H_DIM];  // fc2 K-half 1

// ---------------- PTX helpers (all sm_80-level, no 'a' features) ----------------
__device__ __forceinline__ uint32_t s2u(const void* p) {
    uint32_t a;
    asm("{ .reg .u64 t; cvta.to.shared.u64 t, %1; cvt.u32.u64 %0, t; }" : "=r"(a) : "l"(p));
    return a;
}
__device__ __forceinline__ void cp16(uint32_t dst, const void* src, uint32_t sz) {
    asm volatile("cp.async.cg.shared.global [%0], [%1], 16, %2;" :: "r"(dst), "l"(src), "r"(sz));
}
__device__ __forceinline__ void cp_commit() { asm volatile("cp.async.commit_group;" ::: "memory"); }
template<int N> __device__ __forceinline__ void cp_wait() {
    asm volatile("cp.async.wait_group %0;" :: "n"(N) : "memory");
}
__device__ __forceinline__ void ldsm4(uint32_t r[4], uint32_t addr) {
    asm volatile("ldmatrix.sync.aligned.m8n8.x4.shared.b16 {%0,%1,%2,%3}, [%4];"
        : "=r"(r[0]), "=r"(r[1]), "=r"(r[2]), "=r"(r[3]) : "r"(addr));
}
__device__ __forceinline__ uint32_t f2tf_f(float x) {
    uint32_t r;
    asm("cvt.rna.tf32.f32 %0, %1;" : "=r"(r) : "f"(x));
    return r;
}
__device__ __forceinline__ float tfr(float x) {
    return __uint_as_float(f2tf_f(x));
}
__device__ __forceinline__ void mma8(float* c, const uint32_t* a, uint32_t b0, uint32_t b1) {
    asm volatile(
        "mma.sync.aligned.m16n8k8.row.col.f32.tf32.tf32.f32 "
        "{%0,%1,%2,%3}, {%4,%5,%6,%7}, {%8,%9}, {%0,%1,%2,%3};"
        : "+f"(c[0]), "+f"(c[1]), "+f"(c[2]), "+f"(c[3])
        : "r"(a[0]), "r"(a[1]), "r"(a[2]), "r"(a[3]), "r"(b0), "r"(b1));
}

// ---- gemm1 SMEM: 3 stages of {A 8KB (64x32f swizzled), B 17408B (32 x 136 f)}
#define G1_BPAD 136
#define G1_STAGE 25600
#define G1_OFF_A(b) ((b) * G1_STAGE)
#define G1_OFF_B(b) (G1_OFF_A(b) + 8192)
#define G1_SMEM 76800               // 3 stages; occ-3: 3*(76800+1024) = 228KB exactly
// ---- gemm2 SMEM: 3 stages of {A 16KB (128x32f swizzled), B 17408B}
#define G2_BPAD 136
#define G2_STAGE 33792
#define G2_OFF_A(b) ((b) * G2_STAGE)
#define G2_OFF_B(b) (G2_OFF_A(b) + 16384)
#define G2_SMEM 101376

// ---------------- init: fused cvtx (blocks 0..2047) + setup (block 2048) ----------------
__global__ void __launch_bounds__(256)
init_kernel(const float* __restrict__ x, const int* __restrict__ sel) {
    if (blockIdx.x < 2048) {
        int i = blockIdx.x * 256 + threadIdx.x;          // T*H/4 = 524288 = 2048*256
        float4 v = reinterpret_cast<const float4*>(x)[i];
        v.x = tfr(v.x); v.y = tfr(v.y); v.z = tfr(v.z); v.w = tfr(v.w);
        reinterpret_cast<float4*>(g_xc)[i] = v;
        return;
    }
    // ---- setup: counting sort + both tilings ----
    __shared__ int cnt[E_NUM];
    __shared__ int run[E_NUM];
    int tid = threadIdx.x;
    if (tid < E_NUM) cnt[tid] = 0;
    __syncthreads();
    for (int i = tid; i < NROWS; i += blockDim.x)
        atomicAdd(&cnt[sel[i]], 1);
    __syncthreads();
    if (tid == 0) {
        int s = 0, nt = 0, nt2 = 0;
        for (int e = 0; e < E_NUM; e++) {
            run[e] = s;
            int c = cnt[e];
            for (int r = 0; r < c; r += BM1) {        // BM=64 tiles for gemm1
                g_tile_expert[nt] = e;
                g_tile_row[nt]    = s + r;
                g_tile_end[nt]    = s + c;
                nt++;
            }
            for (int r = 0; r < c; r += 128) {        // BM=128 tiles for gemm2
                g_tile2_expert[nt2] = e;
                g_tile2_row[nt2]    = s + r;
                g_tile2_end[nt2]    = s + c;
                nt2++;
            }
            s += c;
        }
        g_num_tiles = nt;
        g_num_tiles2 = nt2;
    }
    __syncthreads();
    for (int i = tid; i < NROWS; i += blockDim.x) {
        int e = sel[i];
        int p = atomicAdd(&run[e], 1);
        g_row_src[p] = i;
        g_pos[i] = p;
    }
}

// ---------------- GEMM1: act = swiglu( Xc_gather @ W1[e] ) ----------------
// Block: 64 rows x (gate 64 + up 64). Warps 2x4, warp tile 32x32. ks staggered by warpM.
__global__ void __launch_bounds__(256, 3)
gemm1_kernel(const float* __restrict__ w1) {
    extern __shared__ char smem[];
    uint32_t sb = s2u(smem);
    int mt = blockIdx.x;
    if (mt >= g_num_tiles) return;
    int e = g_tile_expert[mt], row0 = g_tile_row[mt], rend = g_tile_end[mt];
    int col0g = blockIdx.y * 64;

    int tid = threadIdx.x, lane = tid & 31, wid = tid >> 5;
    int warpM = wid >> 2, warpN = wid & 3;
    int gid = lane >> 2, tig = lane & 3;

    const float* W = w1 + (size_t)e * H_DIM * (2 * I_DIM);
    int am = tid >> 2;
    int ac0 = (tid & 3) * 2;
    int akey = am & 7;
    int arow = row0 + am;
    int tokm = (arow < rend) ? (g_row_src[arow] / K_TOP) : -1;
    const float* asrc = g_xc + (size_t)(tokm < 0 ? 0 : tokm) * H_DIM;
    uint32_t asz = (tokm < 0) ? 0u : 16u;

    auto load_chunk = [&](int ci, int buf) {
        int k0 = ci * 32;
        uint32_t Ab = sb + G1_OFF_A(buf);
        cp16(Ab + am * 128 + ((ac0 ^ akey) << 4),       asrc + k0 + ac0 * 4, asz);
        cp16(Ab + am * 128 + (((ac0 + 1) ^ akey) << 4), asrc + k0 + ac0 * 4 + 4, asz);
        uint32_t Bb = sb + G1_OFF_B(buf);
        #pragma unroll
        for (int it = 0; it < 4; it++) {
            int q = tid + it * 256;
            int k = q >> 5, c16 = q & 31, n = c16 * 4;
            const float* src = (n < 64)
                ? W + (size_t)(k0 + k) * (2 * I_DIM) + col0g + n
                : W + (size_t)(k0 + k) * (2 * I_DIM) + I_DIM + col0g + (n - 64);
            cp16(Bb + k * (G1_BPAD * 4) + n * 4, src, 16);
        }
        cp_commit();
    };

    int mlane = lane & 15, extra = lane >> 4, key = lane & 7;
    int boff = tig * G1_BPAD + warpN * 32 + gid;
    int ph = 2 * warpM;              // phase stagger across SMSP-coresident warps

    float acc[2][4][4] = {};
    const int NC = H_DIM / 32;   // 64
    load_chunk(0, 0);
    load_chunk(1, 1);
    int bc = 0;
    for (int i = 0; i < NC; i++) {
        cp_wait<1>();
        __syncthreads();
        int bn = bc + 2; if (bn >= 3) bn -= 3;
        if (i + 2 < NC) load_chunk(i + 2, bn);
        else            cp_commit();

        uint32_t Ab = sb + G1_OFF_A(bc);
        const float* Bsp = (const float*)(smem + G1_OFF_B(bc));
        #pragma unroll
        for (int ks = 0; ks < 4; ks++) {
            int kse = (ks + ph) & 3;
            uint32_t a[2][4];
            #pragma unroll
            for (int mi = 0; mi < 2; mi++) {
                uint32_t addr = Ab + (uint32_t)((warpM * 32 + mi * 16 + mlane) * 128
                              + ((((kse << 1) | extra) ^ key) << 4));
                ldsm4(a[mi], addr);
            }
            #pragma unroll
            for (int j = 0; j < 4; j++) {
                uint32_t b0 = f2tf_f(Bsp[boff + kse * (8 * G1_BPAD) + j * 8]);
                uint32_t b1 = f2tf_f(Bsp[boff + kse * (8 * G1_BPAD) + j * 8 + 4 * G1_BPAD]);
                mma8(acc[0][j], a[0], b0, b1);
                mma8(acc[1][j], a[1], b0, b1);
            }
        }
        bc = (bc + 1 == 3) ? 0 : bc + 1;
    }

    // epilogue: frags -> smem (stride 132), then swiglu (tf32-rounded) -> g_act
    __syncthreads();
    float* Es = (float*)smem;
    #pragma unroll
    for (int mi = 0; mi < 2; mi++)
        #pragma unroll
        for (int j = 0; j < 4; j++) {
            int row = warpM * 32 + mi * 16 + gid;
            int col = warpN * 32 + j * 8 + 2 * tig;
            *(float2*)&Es[row * 132 + col]       = make_float2(acc[mi][j][0], acc[mi][j][1]);
            *(float2*)&Es[(row + 8) * 132 + col] = make_float2(acc[mi][j][2], acc[mi][j][3]);
        }
    __syncthreads();

    int rr = tid >> 2;                 // 0..63
    int r  = row0 + rr;
    int cb = (tid & 3) * 16;           // 0,16,32,48
    if (r < rend) {
        float* dst = g_act + (size_t)r * I_DIM + col0g + cb;
        #pragma unroll
        for (int jj = 0; jj < 16; jj += 4) {
            float4 gv = *(float4*)&Es[rr * 132 + cb + jj];
            float4 uv = *(float4*)&Es[rr * 132 + 64 + cb + jj];
            float4 o;
            o.x = tfr(gv.x * (1.0f / (1.0f + __expf(-gv.x))) * uv.x);
            o.y = tfr(gv.y * (1.0f / (1.0f + __expf(-gv.y))) * uv.y);
            o.z = tfr(gv.z * (1.0f / (1.0f + __expf(-gv.z))) * uv.z);
            o.w = tfr(gv.w * (1.0f / (1.0f + __expf(-gv.w))) * uv.w);
            *(float4*)(dst + jj) = o;
        }
    }
}

// ---------------- GEMM2: fc2_half[z] = act @ W2[e][z-half] ----------------
// Tile 128x128, 8 warps (2x4), warp 64x32, 3-stage, ks-staggered, split-K2.
__global__ void __launch_bounds__(256, 2)
gemm2_kernel(const float* __restrict__ w2) {
    const int KH  = I_DIM / 2;   // 384
    const int NCH = KH / 32;     // 12

    extern __shared__ char smem[];
    uint32_t sb = s2u(smem);
    int mt = blockIdx.x;
    if (mt >= g_num_tiles2) return;
    int e = g_tile2_expert[mt], row0 = g_tile2_row[mt], rend = g_tile2_end[mt];
    int col0 = blockIdx.y * 128;
    int kz = blockIdx.z;

    int tid = threadIdx.x, lane = tid & 31, wid = tid >> 5;
    int warpM = wid >> 2, warpN = wid & 3;
    int gid = lane >> 2, tig = lane & 3;

    const float* W = w2 + (size_t)e * I_DIM * H_DIM + (size_t)(kz * KH) * H_DIM + col0;

    int am = tid >> 1;
    int ac0 = (tid & 1) * 4;
    int akey = am & 7;
    int rr = row0 + am; if (rr >= NROWS) rr = NROWS - 1;   // clamp; masked in epilogue
    const float* asrc = g_act + (size_t)rr * I_DIM + kz * KH;

    auto load_chunk = [&](int ci, int buf) {
        int k0 = ci * 32;
        uint32_t Ab = sb + G2_OFF_A(buf);
        #pragma unroll
        for (int c = 0; c < 4; c++) {
            int cc = ac0 + c;
            cp16(Ab + am * 128 + ((cc ^ akey) << 4), asrc + k0 + cc * 4, 16);
        }
        uint32_t Bb = sb + G2_OFF_B(buf);
        #pragma unroll
        for (int it = 0; it < 4; it++) {
            int q = tid + it * 256;
            int k = q >> 5, n = (q & 31) * 4;
            cp16(Bb + k * (G2_BPAD * 4) + n * 4, W + (size_t)(k0 + k) * H_DIM + n, 16);
        }
        cp_commit();
    };

    int mlane = lane & 15, extra = lane >> 4, key = lane & 7;
    int boff = tig * G2_BPAD + warpN * 32 + gid;
    int ph = 2 * warpM;

    float acc[4][4][4] = {};
    load_chunk(0, 0);
    load_chunk(1, 1);
    int bc = 0;
    for (int i = 0; i < NCH; i++) {
        cp_wait<1>();
        __syncthreads();
        int bn = bc + 2; if (bn >= 3) bn -= 3;
        if (i + 2 < NCH) load_chunk(i + 2, bn);
        else             cp_commit();

        uint32_t Ab = sb + G2_OFF_A(bc);
        const float* Bsp = (const float*)(smem + G2_OFF_B(bc));
        #pragma unroll
        for (int ks = 0; ks < 4; ks++) {
            int kse = (ks + ph) & 3;
            uint32_t a[4][4];
            #pragma unroll
            for (int mi = 0; mi < 4; mi++) {
                uint32_t addr = Ab + (uint32_t)((warpM * 64 + mi * 16 + mlane) * 128
                              + ((((kse << 1) | extra) ^ key) << 4));
                ldsm4(a[mi], addr);
            }
            #pragma unroll
            for (int j = 0; j < 4; j++) {
                uint32_t b0 = f2tf_f(Bsp[boff + kse * (8 * G2_BPAD) + j * 8]);
                uint32_t b1 = f2tf_f(Bsp[boff + kse * (8 * G2_BPAD) + j * 8 + 4 * G2_BPAD]);
                #pragma unroll
                for (int mi = 0; mi < 4; mi++)
                    mma8(acc[mi][j], a[mi], b0, b1);
            }
        }
        bc = (bc + 1 == 3) ? 0 : bc + 1;
    }

    // epilogue: direct stores into this K-half's buffer
    float* outb = kz ? g_fc2h1 : g_fc2h0;
    #pragma unroll
    for (int mi = 0; mi < 4; mi++) {
        int row = row0 + warpM * 64 + mi * 16 + gid;
        #pragma unroll
        for (int j = 0; j < 4; j++) {
            int col = col0 + warpN * 32 + j * 8 + 2 * tig;
            if (row < rend)
                *(float2*)&outb[(size_t)row * H_DIM + col] =
                    make_float2(acc[mi][j][0], acc[mi][j][1]);
            if (row + 8 < rend)
                *(float2*)&outb[(size_t)(row + 8) * H_DIM + col] =
                    make_float2(acc[mi][j][2], acc[mi][j][3]);
        }
    }
}

// ---------------- combine: out[t] = w0*(h0+h1)[p0] + w1*(h0+h1)[p1] ----------------
__global__ void __launch_bounds__(256)
combine_kernel(const float* __restrict__ rw, float* __restrict__ out) {
    int i = blockIdx.x * blockDim.x + threadIdx.x;
    if (i >= T_TOK * (H_DIM / 4)) return;
    int t  = i >> 9;
    int h4 = i & 511;
    int p0 = g_pos[2 * t];
    int p1 = g_pos[2 * t + 1];
    float w0 = rw[2 * t];
    float w1 = rw[2 * t + 1];
    size_t o0 = (size_t)p0 * H_DIM + h4 * 4;
    size_t o1 = (size_t)p1 * H_DIM + h4 * 4;
    float4 a0 = *(const float4*)&g_fc2h0[o0];
    float4 b0 = *(const float4*)&g_fc2h1[o0];
    float4 a1 = *(const float4*)&g_fc2h0[o1];
    float4 b1 = *(const float4*)&g_fc2h1[o1];
    float4 o;
    o.x = w0 * (a0.x + b0.x) + w1 * (a1.x + b1.x);
    o.y = w0 * (a0.y + b0.y) + w1 * (a1.y + b1.y);
    o.z = w0 * (a0.z + b0.z) + w1 * (a1.z + b1.z);
    o.w = w0 * (a0.w + b0.w) + w1 * (a1.w + b1.w);
    reinterpret_cast<float4*>(out)[i] = o;
}

// ---------------- launch ----------------
extern "C" void kernel_launch(void* const* d_in, const int* in_sizes, int n_in,
                              void* d_out, int out_size) {
    const float* x   = (const float*)d_in[0];   // hidden_states [T, H]
    const float* rw  = (const float*)d_in[1];   // routing_weights [T, K]
    const float* w1  = (const float*)d_in[2];   // gate_up_proj [E, H, 2I]
    const float* w2  = (const float*)d_in[3];   // down_proj   [E, I, H]
    const int*   sel = (const int*)d_in[4];     // selected_experts [T, K]
    float* out = (float*)d_out;                 // [T, H] fp32

    cudaFuncSetAttribute(gemm1_kernel, cudaFuncAttributeMaxDynamicSharedMemorySize, G1_SMEM);
    cudaFuncSetAttribute(gemm2_kernel, cudaFuncAttributeMaxDynamicSharedMemorySize, G2_SMEM);

    init_kernel<<<2049, 256>>>(x, sel);
    gemm1_kernel<<<dim3(MAX_TILES, I_DIM / 64), 256, G1_SMEM>>>(w1);
    gemm2_kernel<<<dim3(24, H_DIM / 128, 2), 256, G2_SMEM>>>(w2);
    combine_kernel<<<(T_TOK * H_DIM / 4 + 255) / 256, 256>>>(rw, out);
}

// round 15
// speedup vs baseline: 1.9205x; 1.2963x over previous
#include <cuda_runtime.h>
#include <cuda_fp16.h>
#include <cstdint>
#include <cmath>

// Problem constants (fixed by the dataset)
#define T_TOK 1024
#define H_DIM 2048
#define I_DIM 768
#define E_NUM 8
#define K_TOP 2
#define NROWS (T_TOK * K_TOP)      // 2048 permuted rows

#define BM1 64
#define MAX_TILES 40

// ---------------- scratch (no allocations allowed) ----------------
__device__ int    g_row_src[NROWS];
__device__ int    g_pos[NROWS];
__device__ int    g_tile_expert[MAX_TILES];   // BM=64 tiling (gemm1)
__device__ int    g_tile_row[MAX_TILES];
__device__ int    g_tile_end[MAX_TILES];
__device__ int    g_num_tiles;
__device__ int    g_tile2_expert[MAX_TILES];  // BM=128 tiling (gemm2)
__device__ int    g_tile2_row[MAX_TILES];
__device__ int    g_tile2_end[MAX_TILES];
__device__ int    g_num_tiles2;
__device__ __half g_xh[T_TOK * H_DIM];    // fp16 hidden_states
__device__ __half g_act[NROWS * I_DIM];   // fp16 swiglu output
__device__ float  g_fc2h0[NROWS * H_DIM]; // fc2 K-half 0 (fp32)
__device__ float  g_fc2h1[NROWS * H_DIM]; // fc2 K-half 1 (fp32)

// ---------------- PTX helpers (all sm_80-level, no 'a' features) ----------------
__device__ __forceinline__ uint32_t s2u(const void* p) {
    uint32_t a;
    asm("{ .reg .u64 t; cvta.to.shared.u64 t, %1; cvt.u32.u64 %0, t; }" : "=r"(a) : "l"(p));
    return a;
}
__device__ __forceinline__ void cp16(uint32_t dst, const void* src, uint32_t sz) {
    asm volatile("cp.async.cg.shared.global [%0], [%1], 16, %2;" :: "r"(dst), "l"(src), "r"(sz));
}
__device__ __forceinline__ void cp_commit() { asm volatile("cp.async.commit_group;" ::: "memory"); }
template<int N> __device__ __forceinline__ void cp_wait() {
    asm volatile("cp.async.wait_group %0;" :: "n"(N) : "memory");
}
__device__ __forceinline__ void ldsm4(uint32_t r[4], uint32_t addr) {
    asm volatile("ldmatrix.sync.aligned.m8n8.x4.shared.b16 {%0,%1,%2,%3}, [%4];"
        : "=r"(r[0]), "=r"(r[1]), "=r"(r[2]), "=r"(r[3]) : "r"(addr));
}
__device__ __forceinline__ uint32_t pack_h2(float lo, float hi) {
    uint32_t r;
    asm("cvt.rn.f16x2.f32 %0, %1, %2;" : "=r"(r) : "f"(hi), "f"(lo));
    return r;
}
__device__ __forceinline__ void mma16(float* c, const uint32_t* a, uint32_t b0, uint32_t b1) {
    asm volatile(
        "mma.sync.aligned.m16n8k16.row.col.f32.f16.f16.f32 "
        "{%0,%1,%2,%3}, {%4,%5,%6,%7}, {%8,%9}, {%0,%1,%2,%3};"
        : "+f"(c[0]), "+f"(c[1]), "+f"(c[2]), "+f"(c[3])
        : "r"(a[0]), "r"(a[1]), "r"(a[2]), "r"(a[3]), "r"(b0), "r"(b1));
}

// ---- SMEM geometry. A rows: 32 fp16 = 64B, 16B chunks swizzled by ((row>>1)&3).
//      B: fp32 [k][n], 32 k-rows x BPAD floats, BPAD=132 (fp16-pair LDS conflict-free).
#define BPAD 132
#define G1_STAGE 20992              // A 4096 + B 16896
#define G1_OFF_A(b) ((b) * G1_STAGE)
#define G1_OFF_B(b) (G1_OFF_A(b) + 4096)
#define G1_SMEM 62976               // 3 stages; occ-3
#define G2_STAGE 25088              // A 8192 + B 16896
#define G2_OFF_A(b) ((b) * G2_STAGE)
#define G2_OFF_B(b) (G2_OFF_A(b) + 8192)
#define G2_SMEM 75264               // 3 stages; occ-2

// ---------------- init: x -> fp16 (blocks 0..1023) + setup (block 1024) ----------------
__global__ void __launch_bounds__(256)
init_kernel(const float* __restrict__ x, const int* __restrict__ sel) {
    if (blockIdx.x < 1024) {
        int i = blockIdx.x * 256 + threadIdx.x;          // over T*H/8 = 262144
        const float4* xp = reinterpret_cast<const float4*>(x) + 2 * i;
        float4 v0 = xp[0], v1 = xp[1];
        uint4 o;
        o.x = pack_h2(v0.x, v0.y);
        o.y = pack_h2(v0.z, v0.w);
        o.z = pack_h2(v1.x, v1.y);
        o.w = pack_h2(v1.z, v1.w);
        reinterpret_cast<uint4*>(g_xh)[i] = o;
        return;
    }
    __shared__ int cnt[E_NUM];
    __shared__ int run[E_NUM];
    int tid = threadIdx.x;
    if (tid < E_NUM) cnt[tid] = 0;
    __syncthreads();
    for (int i = tid; i < NROWS; i += blockDim.x)
        atomicAdd(&cnt[sel[i]], 1);
    __syncthreads();
    if (tid == 0) {
        int s = 0, nt = 0, nt2 = 0;
        for (int e = 0; e < E_NUM; e++) {
            run[e] = s;
            int c = cnt[e];
            for (int r = 0; r < c; r += BM1) {
                g_tile_expert[nt] = e;
                g_tile_row[nt]    = s + r;
                g_tile_end[nt]    = s + c;
                nt++;
            }
            for (int r = 0; r < c; r += 128) {
                g_tile2_expert[nt2] = e;
                g_tile2_row[nt2]    = s + r;
                g_tile2_end[nt2]    = s + c;
                nt2++;
            }
            s += c;
        }
        g_num_tiles = nt;
        g_num_tiles2 = nt2;
    }
    __syncthreads();
    for (int i = tid; i < NROWS; i += blockDim.x) {
        int e = sel[i];
        int p = atomicAdd(&run[e], 1);
        g_row_src[p] = i;
        g_pos[i] = p;
    }
}

// ---------------- GEMM1: act = swiglu( Xh_gather @ W1[e] ), fp16 mma ----------------
// Block: 64 rows x (gate 64 + up 64). Warps 2x4, warp tile 32x32.
__global__ void __launch_bounds__(256, 3)
gemm1_kernel(const float* __restrict__ w1) {
    extern __shared__ char smem[];
    uint32_t sb = s2u(smem);
    int mt = blockIdx.x;
    if (mt >= g_num_tiles) return;
    int e = g_tile_expert[mt], row0 = g_tile_row[mt], rend = g_tile_end[mt];
    int col0g = blockIdx.y * 64;

    int tid = threadIdx.x, lane = tid & 31, wid = tid >> 5;
    int warpM = wid >> 2, warpN = wid & 3;
    int gid = lane >> 2, tig = lane & 3;

    const float* W = w1 + (size_t)e * H_DIM * (2 * I_DIM);
    // A loader: row am (0..63), chunk c = tid&3 (one cp16, fp16 data)
    int am = tid >> 2;
    int ach = tid & 3;
    int arow = row0 + am;
    int tokm = (arow < rend) ? (g_row_src[arow] / K_TOP) : -1;
    const __half* asrc = g_xh + (size_t)(tokm < 0 ? 0 : tokm) * H_DIM;
    uint32_t asz = (tokm < 0) ? 0u : 16u;
    int adst = am * 64 + ((ach ^ ((am >> 1) & 3)) << 4);

    auto load_chunk = [&](int ci, int buf) {
        int k0 = ci * 32;
        cp16(sb + G1_OFF_A(buf) + adst, asrc + k0 + ach * 8, asz);
        uint32_t Bb = sb + G1_OFF_B(buf);
        #pragma unroll
        for (int it = 0; it < 4; it++) {
            int q = tid + it * 256;
            int k = q >> 5, n = (q & 31) * 4;
            const float* src = (n < 64)
                ? W + (size_t)(k0 + k) * (2 * I_DIM) + col0g + n
                : W + (size_t)(k0 + k) * (2 * I_DIM) + I_DIM + col0g + (n - 64);
            cp16(Bb + k * (BPAD * 4) + n * 4, src, 16);
        }
        cp_commit();
    };

    int mrow_base = warpM * 32 + (lane & 15);
    int aq = lane >> 4;                 // 0/1: k-lo/k-hi 16B chunk within k16
    int boffn = warpN * 32 + gid;

    float acc[2][4][4] = {};
    const int NC = H_DIM / 32;   // 64
    load_chunk(0, 0);
    load_chunk(1, 1);
    int bc = 0;
    for (int i = 0; i < NC; i++) {
        cp_wait<1>();
        __syncthreads();
        int bn = bc + 2; if (bn >= 3) bn -= 3;
        if (i + 2 < NC) load_chunk(i + 2, bn);
        else            cp_commit();

        uint32_t Ab = sb + G1_OFF_A(bc);
        const float* Bsp = (const float*)(smem + G1_OFF_B(bc));
        #pragma unroll
        for (int ks = 0; ks < 2; ks++) {         // 2 x k16 per 32-chunk
            int kse = (ks + warpM) & 1;          // phase stagger
            uint32_t a[2][4];
            #pragma unroll
            for (int mi = 0; mi < 2; mi++) {
                int mrow = mrow_base + mi * 16;
                int c0 = kse * 2 + aq;
                ldsm4(a[mi], Ab + mrow * 64 + ((c0 ^ ((mrow >> 1) & 3)) << 4));
            }
            int kb = kse * 16 + tig * 2;
            #pragma unroll
            for (int j = 0; j < 4; j++) {
                int n = boffn + j * 8;
                uint32_t b0 = pack_h2(Bsp[kb * BPAD + n],       Bsp[(kb + 1) * BPAD + n]);
                uint32_t b1 = pack_h2(Bsp[(kb + 8) * BPAD + n], Bsp[(kb + 9) * BPAD + n]);
                mma16(acc[0][j], a[0], b0, b1);
                mma16(acc[1][j], a[1], b0, b1);
            }
        }
        bc = (bc + 1 == 3) ? 0 : bc + 1;
    }

    // epilogue: frags -> smem (fp32, stride 132), swiglu -> g_act (fp16)
    __syncthreads();
    float* Es = (float*)smem;
    #pragma unroll
    for (int mi = 0; mi < 2; mi++)
        #pragma unroll
        for (int j = 0; j < 4; j++) {
            int row = warpM * 32 + mi * 16 + gid;
            int col = warpN * 32 + j * 8 + 2 * tig;
            *(float2*)&Es[row * 132 + col]       = make_float2(acc[mi][j][0], acc[mi][j][1]);
            *(float2*)&Es[(row + 8) * 132 + col] = make_float2(acc[mi][j][2], acc[mi][j][3]);
        }
    __syncthreads();

    int rr = tid >> 2;                 // 0..63
    int r  = row0 + rr;
    int cb = (tid & 3) * 16;           // 0,16,32,48
    if (r < rend) {
        __half* dst = g_act + (size_t)r * I_DIM + col0g + cb;
        #pragma unroll
        for (int jj = 0; jj < 16; jj += 4) {
            float4 gv = *(float4*)&Es[rr * 132 + cb + jj];
            float4 uv = *(float4*)&Es[rr * 132 + 64 + cb + jj];
            float o0 = gv.x * (1.0f / (1.0f + __expf(-gv.x))) * uv.x;
            float o1 = gv.y * (1.0f / (1.0f + __expf(-gv.y))) * uv.y;
            float o2 = gv.z * (1.0f / (1.0f + __expf(-gv.z))) * uv.z;
            float o3 = gv.w * (1.0f / (1.0f + __expf(-gv.w))) * uv.w;
            uint2 oo;
            oo.x = pack_h2(o0, o1);
            oo.y = pack_h2(o2, o3);
            *(uint2*)(dst + jj) = oo;
        }
    }
}

// ---------------- GEMM2: fc2_half[z] = act @ W2[e][z-half], fp16 mma, split-K2 ----------------
// Tile 128x128, 8 warps (2x4), warp 64x32.
__global__ void __launch_bounds__(256, 2)
gemm2_kernel(const float* __restrict__ w2) {
    const int KH  = I_DIM / 2;   // 384
    const int NCH = KH / 32;     // 12

    extern __shared__ char smem[];
    uint32_t sb = s2u(smem);
    int mt = blockIdx.x;
    if (mt >= g_num_tiles2) return;
    int e = g_tile2_expert[mt], row0 = g_tile2_row[mt], rend = g_tile2_end[mt];
    int col0 = blockIdx.y * 128;
    int kz = blockIdx.z;

    int tid = threadIdx.x, lane = tid & 31, wid = tid >> 5;
    int warpM = wid >> 2, warpN = wid & 3;
    int gid = lane >> 2, tig = lane & 3;

    const float* W = w2 + (size_t)e * I_DIM * H_DIM + (size_t)(kz * KH) * H_DIM + col0;

    // A loader: row am (0..127), 2 chunks (tid&1)*2..+1
    int am = tid >> 1;
    int ac0 = (tid & 1) * 2;
    int rr = row0 + am; if (rr >= NROWS) rr = NROWS - 1;   // clamp; masked in epilogue
    const __half* asrc = g_act + (size_t)rr * I_DIM + kz * KH;
    int akey = (am >> 1) & 3;

    auto load_chunk = [&](int ci, int buf) {
        int k0 = ci * 32;
        uint32_t Ab = sb + G2_OFF_A(buf);
        cp16(Ab + am * 64 + ((ac0 ^ akey) << 4),       asrc + k0 + ac0 * 8, 16);
        cp16(Ab + am * 64 + (((ac0 + 1) ^ akey) << 4), asrc + k0 + ac0 * 8 + 8, 16);
        uint32_t Bb = sb + G2_OFF_B(buf);
        #pragma unroll
        for (int it = 0; it < 4; it++) {
            int q = tid + it * 256;
            int k = q >> 5, n = (q & 31) * 4;
            cp16(Bb + k * (BPAD * 4) + n * 4, W + (size_t)(k0 + k) * H_DIM + n, 16);
        }
        cp_commit();
    };

    int mrow_base = warpM * 64 + (lane & 15);
    int aq = lane >> 4;
    int boffn = warpN * 32 + gid;

    float acc[4][4][4] = {};
    load_chunk(0, 0);
    load_chunk(1, 1);
    int bc = 0;
    for (int i = 0; i < NCH; i++) {
        cp_wait<1>();
        __syncthreads();
        int bn = bc + 2; if (bn >= 3) bn -= 3;
        if (i + 2 < NCH) load_chunk(i + 2, bn);
        else             cp_commit();

        uint32_t Ab = sb + G2_OFF_A(bc);
        const float* Bsp = (const float*)(smem + G2_OFF_B(bc));
        #pragma unroll
        for (int ks = 0; ks < 2; ks++) {
            int kse = (ks + warpM) & 1;
            uint32_t a[4][4];
            #pragma unroll
            for (int mi = 0; mi < 4; mi++) {
                int mrow = mrow_base + mi * 16;
                int c0 = kse * 2 + aq;
                ldsm4(a[mi], Ab + mrow * 64 + ((c0 ^ ((mrow >> 1) & 3)) << 4));
            }
            int kb = kse * 16 + tig * 2;
            #pragma unroll
            for (int j = 0; j < 4; j++) {
                int n = boffn + j * 8;
                uint32_t b0 = pack_h2(Bsp[kb * BPAD + n],       Bsp[(kb + 1) * BPAD + n]);
                uint32_t b1 = pack_h2(Bsp[(kb + 8) * BPAD + n], Bsp[(kb + 9) * BPAD + n]);
                #pragma unroll
                for (int mi = 0; mi < 4; mi++)
                    mma16(acc[mi][j], a[mi], b0, b1);
            }
        }
        bc = (bc + 1 == 3) ? 0 : bc + 1;
    }

    // epilogue: direct stores into this K-half's buffer (fp32)
    float* outb = kz ? g_fc2h1 : g_fc2h0;
    #pragma unroll
    for (int mi = 0; mi < 4; mi++) {
        int row = row0 + warpM * 64 + mi * 16 + gid;
        #pragma unroll
        for (int j = 0; j < 4; j++) {
            int col = col0 + warpN * 32 + j * 8 + 2 * tig;
            if (row < rend)
                *(float2*)&outb[(size_t)row * H_DIM + col] =
                    make_float2(acc[mi][j][0], acc[mi][j][1]);
            if (row + 8 < rend)
                *(float2*)&outb[(size_t)(row + 8) * H_DIM + col] =
                    make_float2(acc[mi][j][2], acc[mi][j][3]);
        }
    }
}

// ---------------- combine: out[t] = w0*(h0+h1)[p0] + w1*(h0+h1)[p1] ----------------
__global__ void __launch_bounds__(256)
combine_kernel(const float* __restrict__ rw, float* __restrict__ out) {
    int i = blockIdx.x * blockDim.x + threadIdx.x;
    if (i >= T_TOK * (H_DIM / 4)) return;
    int t  = i >> 9;
    int h4 = i & 511;
    int p0 = g_pos[2 * t];
    int p1 = g_pos[2 * t + 1];
    float w0 = rw[2 * t];
    float w1 = rw[2 * t + 1];
    size_t o0 = (size_t)p0 * H_DIM + h4 * 4;
    size_t o1 = (size_t)p1 * H_DIM + h4 * 4;
    float4 a0 = *(const float4*)&g_fc2h0[o0];
    float4 b0 = *(const float4*)&g_fc2h1[o0];
    float4 a1 = *(const float4*)&g_fc2h0[o1];
    float4 b1 = *(const float4*)&g_fc2h1[o1];
    float4 o;
    o.x = w0 * (a0.x + b0.x) + w1 * (a1.x + b1.x);
    o.y = w0 * (a0.y + b0.y) + w1 * (a1.y + b1.y);
    o.z = w0 * (a0.z + b0.z) + w1 * (a1.z + b1.z);
    o.w = w0 * (a0.w + b0.w) + w1 * (a1.w + b1.w);
    reinterpret_cast<float4*>(out)[i] = o;
}

// ---------------- launch ----------------
extern "C" void kernel_launch(void* const* d_in, const int* in_sizes, int n_in,
                              void* d_out, int out_size) {
    const float* x   = (const float*)d_in[0];   // hidden_states [T, H]
    const float* rw  = (const float*)d_in[1];   // routing_weights [T, K]
    const float* w1  = (const float*)d_in[2];   // gate_up_proj [E, H, 2I]
    const float* w2  = (const float*)d_in[3];   // down_proj   [E, I, H]
    const int*   sel = (const int*)d_in[4];     // selected_experts [T, K]
    float* out = (float*)d_out;                 // [T, H] fp32

    cudaFuncSetAttribute(gemm1_kernel, cudaFuncAttributeMaxDynamicSharedMemorySize, G1_SMEM);
    cudaFuncSetAttribute(gemm2_kernel, cudaFuncAttributeMaxDynamicSharedMemorySize, G2_SMEM);

    init_kernel<<<1025, 256>>>(x, sel);
    gemm1_kernel<<<dim3(MAX_TILES, I_DIM / 64), 256, G1_SMEM>>>(w1);
    gemm2_kernel<<<dim3(24, H_DIM / 128, 2), 256, G2_SMEM>>>(w2);
    combine_kernel<<<(T_TOK * H_DIM / 4 + 255) / 256, 256>>>(rw, out);
}